// round 15
// baseline (speedup 1.0000x reference)
#include <cuda_runtime.h>
#include <cstdint>

#define G_ 16384
#define D_ 128
#define R_ 32
#define H_ 256
#define O_ 64

// B fragments fp16: idx = (nt*8 + kg)*32 + lane, payload {bhi0, bhi1, blo0, blo1}
__device__ uint4  g_Bfrag[32 * 32];
__device__ float2 g_Mtp[R_ * 32];   // {Mt[r][o], Mt[r][o+32]}, Mt=(Wl@V)^T

// pack two floats -> f16x2 (x0 -> low half / element k, x1 -> high half / k+1)
__device__ __forceinline__ uint32_t pack2(float x0, float x1) {
    uint32_t r;
    asm("cvt.rn.f16x2.f32 %0, %1, %2;" : "=r"(r) : "f"(x1), "f"(x0));
    return r;
}
__device__ __forceinline__ float2 unpack2(uint32_t h) {
    float lo, hi;
    asm("{.reg .b16 l, h; mov.b32 {l, h}, %2; cvt.f32.f16 %0, l; cvt.f32.f16 %1, h;}"
        : "=f"(lo), "=f"(hi) : "r"(h));
    return make_float2(lo, hi);
}

// grid 64 x 256 = 16384 threads
__global__ void prep_kernel(const float* __restrict__ V,
                            const float* __restrict__ Wl,
                            const float* __restrict__ W) {
    int t = blockIdx.x * blockDim.x + threadIdx.x;
    if (t < 1024) {
        int l = t & 31, kg = (t >> 5) & 7, nt = t >> 8;
        int k0 = kg * 16 + (l & 3) * 2;
        int n = nt * 8 + (l >> 2);
        float b00 = W[k0 * R_ + n],       b01 = W[(k0 + 1) * R_ + n];
        float b10 = W[(k0 + 8) * R_ + n], b11 = W[(k0 + 9) * R_ + n];
        uint4 pk;
        pk.x = pack2(b00, b01);
        pk.y = pack2(b10, b11);
        float2 f0 = unpack2(pk.x), f1 = unpack2(pk.y);
        pk.z = pack2(b00 - f0.x, b01 - f0.y);
        pk.w = pack2(b10 - f1.x, b11 - f1.y);
        g_Bfrag[t] = pk;
    }
    int u = t >> 3, seg = t & 7;
    int rr = u >> 6, rem = u & 63;
    const float* wl = Wl + rem * H_ + seg * 32;
    const float* vp = V + seg * 32 * R_ + rr;
    float acc = 0.f;
#pragma unroll
    for (int i = 0; i < 32; ++i)
        acc = fmaf(wl[i], vp[i * R_], acc);
#pragma unroll
    for (int m = 1; m <= 4; m <<= 1)
        acc += __shfl_xor_sync(0xffffffffu, acc, m);
    if (seg == 0)
        ((float*)g_Mtp)[rr * 64 + (rem & 31) * 2 + (rem >> 5)] = acc;
}

#define SM_TOTAL 16384   // only B fragments

#define MMAH(c, a0, a1, a2, a3, b0, b1)                                        \
    asm volatile("mma.sync.aligned.m16n8k16.row.col.f32.f16.f16.f32 "          \
                 "{%0,%1,%2,%3}, {%4,%5,%6,%7}, {%8,%9}, {%0,%1,%2,%3};"       \
                 : "+f"(c[0]), "+f"(c[1]), "+f"(c[2]), "+f"(c[3])              \
                 : "r"(a0), "r"(a1), "r"(a2), "r"(a3), "r"(b0), "r"(b1))

extern __shared__ __align__(16) char smc[];

// CTA = 8 warps, warp = 1 graph, grid = 2048; 2 CTAs/SM (reg-capped).
// A fragments loaded DIRECTLY from gmem (sector-coalesced, each byte read once);
// 1-deep software pipeline covers latency. No smem for A.
__global__ void __launch_bounds__(256, 2)
main_kernel(const float* __restrict__ hin, const float* __restrict__ bl,
            float* __restrict__ out) {
    const int t = threadIdx.x;
    const int w = t >> 5;
    const int l = t & 31;

    // ---- stage B fragments (whole CTA) ----
    {
        uint4* sB = (uint4*)smc;
#pragma unroll
        for (int j = 0; j < 4; ++j) sB[j * 256 + t] = g_Bfrag[j * 256 + t];
    }
    __syncthreads();

    const int g = blockIdx.x * 8 + w;
    const float* hb = hin + (size_t)g * (32 * D_);

    const int r4 = l >> 2, lc = l & 3;

    // row pointers for this thread's 4 fragment rows (r4 + 8j), at k-offset 2*lc
    const float2* rp0 = (const float2*)(hb + (r4 +  0) * D_ + 2 * lc);
    const float2* rp1 = (const float2*)(hb + (r4 +  8) * D_ + 2 * lc);
    const float2* rp2 = (const float2*)(hb + (r4 + 16) * D_ + 2 * lc);
    const float2* rp3 = (const float2*)(hb + (r4 + 24) * D_ + 2 * lc);

    float c[2][4][4];
#pragma unroll
    for (int mt = 0; mt < 2; ++mt)
#pragma unroll
        for (int nt = 0; nt < 4; ++nt)
#pragma unroll
            for (int i = 0; i < 4; ++i) c[mt][nt][i] = 0.f;

    // cur[j*2+0] = row j, k 2lc..2lc+1 ; cur[j*2+1] = row j, k 2lc+8..2lc+9
    float2 cur[8];
    cur[0] = rp0[0]; cur[1] = rp0[4];
    cur[2] = rp1[0]; cur[3] = rp1[4];
    cur[4] = rp2[0]; cur[5] = rp2[4];
    cur[6] = rp3[0]; cur[7] = rp3[4];

#pragma unroll
    for (int kg = 0; kg < 8; ++kg) {
        // prefetch next k16 chunk (independent -> ptxas front-batches these LDGs)
        float2 nxt[8];
        if (kg < 7) {
            const int o = (kg + 1) * 8;
            nxt[0] = rp0[o]; nxt[1] = rp0[o + 4];
            nxt[2] = rp1[o]; nxt[3] = rp1[o + 4];
            nxt[4] = rp2[o]; nxt[5] = rp2[o + 4];
            nxt[6] = rp3[o]; nxt[7] = rp3[o + 4];
        }

        // B fragments for this k16 step
        uint4 bv[4];
#pragma unroll
        for (int nt = 0; nt < 4; ++nt)
            bv[nt] = ((const uint4*)smc)[(nt * 8 + kg) * 32 + l];

        // split cur -> fp16 hi/lo fragments
        uint32_t ahi[2][4], alo[2][4];
#pragma unroll
        for (int mt = 0; mt < 2; ++mt) {
            float2 p0 = cur[(2 * mt + 0) * 2 + 0];   // row lower, k
            float2 p1 = cur[(2 * mt + 1) * 2 + 0];   // row upper, k
            float2 p2 = cur[(2 * mt + 0) * 2 + 1];   // row lower, k+8
            float2 p3 = cur[(2 * mt + 1) * 2 + 1];   // row upper, k+8
            ahi[mt][0] = pack2(p0.x, p0.y);
            ahi[mt][1] = pack2(p1.x, p1.y);
            ahi[mt][2] = pack2(p2.x, p2.y);
            ahi[mt][3] = pack2(p3.x, p3.y);
            float2 f;
            f = unpack2(ahi[mt][0]); alo[mt][0] = pack2(p0.x - f.x, p0.y - f.y);
            f = unpack2(ahi[mt][1]); alo[mt][1] = pack2(p1.x - f.x, p1.y - f.y);
            f = unpack2(ahi[mt][2]); alo[mt][2] = pack2(p2.x - f.x, p2.y - f.y);
            f = unpack2(ahi[mt][3]); alo[mt][3] = pack2(p3.x - f.x, p3.y - f.y);
        }

        // 24 MMAs: hi*bhi + hi*blo + lo*bhi
#pragma unroll
        for (int mt = 0; mt < 2; ++mt)
#pragma unroll
            for (int nt = 0; nt < 4; ++nt) {
                MMAH(c[mt][nt], ahi[mt][0], ahi[mt][1], ahi[mt][2], ahi[mt][3],
                     bv[nt].x, bv[nt].y);
                MMAH(c[mt][nt], ahi[mt][0], ahi[mt][1], ahi[mt][2], ahi[mt][3],
                     bv[nt].z, bv[nt].w);
                MMAH(c[mt][nt], alo[mt][0], alo[mt][1], alo[mt][2], alo[mt][3],
                     bv[nt].x, bv[nt].y);
            }

        if (kg < 7) {
#pragma unroll
            for (int j = 0; j < 8; ++j) cur[j] = nxt[j];
        }
    }

    // ---- pooling: product over 32 nodes, all in registers ----
    float pv[8];
#pragma unroll
    for (int nt = 0; nt < 4; ++nt)
#pragma unroll
        for (int b = 0; b < 2; ++b)
            pv[nt * 2 + b] = c[0][nt][b] * c[0][nt][b + 2] *
                             c[1][nt][b] * c[1][nt][b + 2];
#pragma unroll
    for (int m = 4; m <= 16; m <<= 1)
#pragma unroll
        for (int i = 0; i < 8; ++i)
            pv[i] *= __shfl_xor_sync(0xffffffffu, pv[i], m);

    // ---- epilogue: score[o] = bl[o] + sum_r pooled[r]*Mt[r][o]; lane -> (o, o+32) ----
    unsigned long long s2;
    {
        float b0 = bl[l], b1 = bl[l + 32];
        asm("mov.b64 %0, {%1, %2};" : "=l"(s2) : "f"(b0), "f"(b1));
    }
#pragma unroll
    for (int r = 0; r < R_; ++r) {
        float pvv = __shfl_sync(0xffffffffu, pv[(r >> 3) * 2 + (r & 1)], (r & 7) >> 1);
        unsigned long long pp, mm;
        asm("mov.b64 %0, {%1, %1};" : "=l"(pp) : "f"(pvv));
        mm = __ldg((const unsigned long long*)&g_Mtp[r * 32 + l]);
        asm("fma.rn.f32x2 %0, %1, %2, %0;" : "+l"(s2) : "l"(pp), "l"(mm));
    }
    float s0, s1;
    asm("mov.b64 {%0, %1}, %2;" : "=f"(s0), "=f"(s1) : "l"(s2));
    out[(size_t)g * O_ + l] = s0;
    out[(size_t)g * O_ + l + 32] = s1;
}

extern "C" void kernel_launch(void* const* d_in, const int* in_sizes, int n_in,
                              void* d_out, int out_size) {
    const float* h  = (const float*)d_in[0];
    const float* W  = (const float*)d_in[1];
    const float* V  = (const float*)d_in[2];
    const float* Wl = (const float*)d_in[3];
    const float* bl = (const float*)d_in[4];
    float* out = (float*)d_out;

    static int attr_set = 0;
    if (!attr_set) {
        cudaFuncSetAttribute(main_kernel, cudaFuncAttributeMaxDynamicSharedMemorySize, SM_TOTAL);
        attr_set = 1;
    }

    prep_kernel<<<64, 256>>>(V, Wl, W);
    main_kernel<<<G_ / 8, 256, SM_TOTAL>>>(h, bl, out);
}

// round 16
// speedup vs baseline: 1.1712x; 1.1712x over previous
#include <cuda_runtime.h>
#include <cstdint>

#define G_ 16384
#define D_ 128
#define R_ 32
#define H_ 256
#define O_ 64

// B fragments fp16: idx = (nt*8 + kg)*32 + lane, payload {bhi0, bhi1, blo0, blo1}
__device__ uint4  g_Bfrag[32 * 32];
__device__ float2 g_Mtp[R_ * 32];   // {Mt[r][o], Mt[r][o+32]}, Mt=(Wl@V)^T

// pack two floats -> f16x2 (x0 -> low half / element k, x1 -> high half / k+1)
__device__ __forceinline__ uint32_t pack2(float x0, float x1) {
    uint32_t r;
    asm("cvt.rn.f16x2.f32 %0, %1, %2;" : "=r"(r) : "f"(x1), "f"(x0));
    return r;
}
__device__ __forceinline__ float2 unpack2(uint32_t h) {
    float lo, hi;
    asm("{.reg .b16 l, h; mov.b32 {l, h}, %2; cvt.f32.f16 %0, l; cvt.f32.f16 %1, h;}"
        : "=f"(lo), "=f"(hi) : "r"(h));
    return make_float2(lo, hi);
}

// grid 64 x 256 = 16384 threads
__global__ void prep_kernel(const float* __restrict__ V,
                            const float* __restrict__ Wl,
                            const float* __restrict__ W) {
    int t = blockIdx.x * blockDim.x + threadIdx.x;
    if (t < 1024) {
        int l = t & 31, kg = (t >> 5) & 7, nt = t >> 8;
        int k0 = kg * 16 + (l & 3) * 2;
        int n = nt * 8 + (l >> 2);
        float b00 = W[k0 * R_ + n],       b01 = W[(k0 + 1) * R_ + n];
        float b10 = W[(k0 + 8) * R_ + n], b11 = W[(k0 + 9) * R_ + n];
        uint4 pk;
        pk.x = pack2(b00, b01);
        pk.y = pack2(b10, b11);
        float2 f0 = unpack2(pk.x), f1 = unpack2(pk.y);
        pk.z = pack2(b00 - f0.x, b01 - f0.y);
        pk.w = pack2(b10 - f1.x, b11 - f1.y);
        g_Bfrag[t] = pk;
    }
    int u = t >> 3, seg = t & 7;
    int rr = u >> 6, rem = u & 63;
    const float* wl = Wl + rem * H_ + seg * 32;
    const float* vp = V + seg * 32 * R_ + rr;
    float acc = 0.f;
#pragma unroll
    for (int i = 0; i < 32; ++i)
        acc = fmaf(wl[i], vp[i * R_], acc);
#pragma unroll
    for (int m = 1; m <= 4; m <<= 1)
        acc += __shfl_xor_sync(0xffffffffu, acc, m);
    if (seg == 0)
        ((float*)g_Mtp)[rr * 64 + (rem & 31) * 2 + (rem >> 5)] = acc;
}

// ---- smem layout (bytes) ----
//  sB  [0, 16384)          32x32 uint4 B fragments
//  sA  16384 + w*10240     per warp: 2 ring buffers x (32 rows x 40 floats) = 2 x 5120 B
//  Row stride 40 floats (160B): fragment LDS.64 banks = 8*r4 + 2*lc per phase
//  -> perfect bank permutation, conflict-free.
#define ROWF     40
#define CHUNKB   5120
#define SA_OFF   16384
#define SM_TOTAL (16384 + 8 * 2 * CHUNKB)   // 98304 B -> 2 CTAs/SM

__device__ __forceinline__ uint32_t smem_u32(const void* p) {
    uint32_t a;
    asm("{ .reg .u64 t; cvta.to.shared.u64 t, %1; cvt.u32.u64 %0, t; }" : "=r"(a) : "l"(p));
    return a;
}

#define MMAH(c, a0, a1, a2, a3, b0, b1)                                        \
    asm volatile("mma.sync.aligned.m16n8k16.row.col.f32.f16.f16.f32 "          \
                 "{%0,%1,%2,%3}, {%4,%5,%6,%7}, {%8,%9}, {%0,%1,%2,%3};"       \
                 : "+f"(c[0]), "+f"(c[1]), "+f"(c[2]), "+f"(c[3])              \
                 : "r"(a0), "r"(a1), "r"(a2), "r"(a3), "r"(b0), "r"(b1))

#define CPASYNC(dst, src) \
    asm volatile("cp.async.cg.shared.global [%0], [%1], 16;" :: "r"(dst), "l"(src))
#define CPCOMMIT() asm volatile("cp.async.commit_group;" ::: "memory")
#define CPWAIT(n)  asm volatile("cp.async.wait_group %0;" :: "n"(n) : "memory")

extern __shared__ __align__(16) char smc[];

// CTA = 8 warps, warp = 1 graph, grid = 2048; 2 CTAs/SM.
// K in 4 chunks of 32 cols, double-buffered cp.async.
__global__ void __launch_bounds__(256, 2)
main_kernel(const float* __restrict__ hin, const float* __restrict__ bl,
            float* __restrict__ out) {
    const int t = threadIdx.x;
    const int w = t >> 5;
    const int l = t & 31;

    // ---- stage B fragments (whole CTA) ----
    {
        uint4* sB = (uint4*)smc;
#pragma unroll
        for (int j = 0; j < 4; ++j) sB[j * 256 + t] = g_Bfrag[j * 256 + t];
    }
    __syncthreads();

    float* sA = (float*)(smc + SA_OFF + w * 2 * CHUNKB);
    const uint32_t sAu = smem_u32(sA);

    const int g = blockIdx.x * 8 + w;
    const float* hb = hin + (size_t)g * (32 * D_);

    const int r4 = l >> 2, lc = l & 3;
    const int srow = l >> 3;           // staging: 4 rows per instr (j*4 + srow)
    const int scol = (l & 7) * 4;      // staging: float col within 128B row chunk

    float c[2][4][4];
#pragma unroll
    for (int mt = 0; mt < 2; ++mt)
#pragma unroll
        for (int nt = 0; nt < 4; ++nt)
#pragma unroll
            for (int i = 0; i < 4; ++i) c[mt][nt][i] = 0.f;

    // ---- prologue: stage chunk 0 into buf 0 ----
#pragma unroll
    for (int j = 0; j < 8; ++j) {
        int row = j * 4 + srow;
        CPASYNC(sAu + (row * ROWF + scol) * 4, hb + row * D_ + scol);
    }
    CPCOMMIT();

#pragma unroll
    for (int ch = 0; ch < 4; ++ch) {
        const int buf = ch & 1;
        if (ch < 3) {   // stage chunk ch+1 into other buffer
            uint32_t dbase = sAu + (buf ^ 1) * CHUNKB;
            const float* src = hb + (ch + 1) * 32;
#pragma unroll
            for (int j = 0; j < 8; ++j) {
                int row = j * 4 + srow;
                CPASYNC(dbase + (row * ROWF + scol) * 4, src + row * D_ + scol);
            }
            CPCOMMIT();
            CPWAIT(1);
        } else {
            CPWAIT(0);
        }
        __syncwarp();

        const float* A = sA + buf * (CHUNKB / 4);

#pragma unroll
        for (int s = 0; s < 2; ++s) {
            const int kg = ch * 2 + s;

            // B fragments for this k16 step
            uint4 bv[4];
#pragma unroll
            for (int nt = 0; nt < 4; ++nt)
                bv[nt] = ((const uint4*)smc)[(nt * 8 + kg) * 32 + l];

            // A fragments from smem (conflict-free) + fp16 hi/lo split
            uint32_t ahi[2][4], alo[2][4];
#pragma unroll
            for (int mt = 0; mt < 2; ++mt) {
                const float* r0 = A + (mt * 16 + r4) * ROWF + s * 16 + 2 * lc;
                const float* r1 = r0 + 8 * ROWF;
                float2 p0 = *(const float2*)(r0);
                float2 p1 = *(const float2*)(r1);
                float2 p2 = *(const float2*)(r0 + 8);
                float2 p3 = *(const float2*)(r1 + 8);
                ahi[mt][0] = pack2(p0.x, p0.y);
                ahi[mt][1] = pack2(p1.x, p1.y);
                ahi[mt][2] = pack2(p2.x, p2.y);
                ahi[mt][3] = pack2(p3.x, p3.y);
                float2 f;
                f = unpack2(ahi[mt][0]); alo[mt][0] = pack2(p0.x - f.x, p0.y - f.y);
                f = unpack2(ahi[mt][1]); alo[mt][1] = pack2(p1.x - f.x, p1.y - f.y);
                f = unpack2(ahi[mt][2]); alo[mt][2] = pack2(p2.x - f.x, p2.y - f.y);
                f = unpack2(ahi[mt][3]); alo[mt][3] = pack2(p3.x - f.x, p3.y - f.y);
            }

            // 24 MMAs: hi*bhi + hi*blo + lo*bhi
#pragma unroll
            for (int mt = 0; mt < 2; ++mt)
#pragma unroll
                for (int nt = 0; nt < 4; ++nt) {
                    MMAH(c[mt][nt], ahi[mt][0], ahi[mt][1], ahi[mt][2], ahi[mt][3],
                         bv[nt].x, bv[nt].y);
                    MMAH(c[mt][nt], ahi[mt][0], ahi[mt][1], ahi[mt][2], ahi[mt][3],
                         bv[nt].z, bv[nt].w);
                    MMAH(c[mt][nt], alo[mt][0], alo[mt][1], alo[mt][2], alo[mt][3],
                         bv[nt].x, bv[nt].y);
                }
        }
        __syncwarp();   // done reading buf before next overwrite
    }

    // ---- pooling: product over 32 nodes, all in registers ----
    float pv[8];
#pragma unroll
    for (int nt = 0; nt < 4; ++nt)
#pragma unroll
        for (int b = 0; b < 2; ++b)
            pv[nt * 2 + b] = c[0][nt][b] * c[0][nt][b + 2] *
                             c[1][nt][b] * c[1][nt][b + 2];
#pragma unroll
    for (int m = 4; m <= 16; m <<= 1)
#pragma unroll
        for (int i = 0; i < 8; ++i)
            pv[i] *= __shfl_xor_sync(0xffffffffu, pv[i], m);

    // ---- epilogue: score[o] = bl[o] + sum_r pooled[r]*Mt[r][o]; lane -> (o, o+32) ----
    unsigned long long s2;
    {
        float b0 = bl[l], b1 = bl[l + 32];
        asm("mov.b64 %0, {%1, %2};" : "=l"(s2) : "f"(b0), "f"(b1));
    }
#pragma unroll
    for (int r = 0; r < R_; ++r) {
        float pvv = __shfl_sync(0xffffffffu, pv[(r >> 3) * 2 + (r & 1)], (r & 7) >> 1);
        unsigned long long pp, mm;
        asm("mov.b64 %0, {%1, %1};" : "=l"(pp) : "f"(pvv));
        mm = __ldg((const unsigned long long*)&g_Mtp[r * 32 + l]);
        asm("fma.rn.f32x2 %0, %1, %2, %0;" : "+l"(s2) : "l"(pp), "l"(mm));
    }
    float s0, s1;
    asm("mov.b64 {%0, %1}, %2;" : "=f"(s0), "=f"(s1) : "l"(s2));
    out[(size_t)g * O_ + l] = s0;
    out[(size_t)g * O_ + l + 32] = s1;
}

extern "C" void kernel_launch(void* const* d_in, const int* in_sizes, int n_in,
                              void* d_out, int out_size) {
    const float* h  = (const float*)d_in[0];
    const float* W  = (const float*)d_in[1];
    const float* V  = (const float*)d_in[2];
    const float* Wl = (const float*)d_in[3];
    const float* bl = (const float*)d_in[4];
    float* out = (float*)d_out;

    static int attr_set = 0;
    if (!attr_set) {
        cudaFuncSetAttribute(main_kernel, cudaFuncAttributeMaxDynamicSharedMemorySize, SM_TOTAL);
        attr_set = 1;
    }

    prep_kernel<<<64, 256>>>(V, Wl, W);
    main_kernel<<<G_ / 8, 256, SM_TOTAL>>>(h, bl, out);
}